// round 2
// baseline (speedup 1.0000x reference)
#include <cuda_runtime.h>
#include <math.h>

#define Nn 8192
#define DIN 64
#define DHID 128
#define DE 16
#define NH 4
#define TOPK 7
#define EK (Nn*TOPK)
#define ET (EK+Nn)
#define HF (NH*DHID)
#define NCHUNK 16
#define CHUNK (Nn/NCHUNK)
#define BNS 0.9999950000374997f

#define OUT0_OFF 0
#define OUT1_OFF (Nn*64)
#define EI_OFF (OUT1_OFF + Nn*16)
#define LL_OFF (EI_OFF + 2*ET)

// -------- device scratch (no allocs allowed) --------
__device__ float g_tmp128[Nn*DHID];
__device__ float g_emb[Nn*DE];
__device__ float g_P[Nn*DE];
__device__ float g_ptv[Nn*NCHUNK*TOPK];
__device__ int   g_pti[Nn*NCHUNK*TOPK];
__device__ int   g_sel[Nn*TOPK];
__device__ int   g_src[ET];
__device__ int   g_dst[ET];
__device__ int   g_val[ET];
__device__ int   g_deg[Nn];
__device__ int   g_off[Nn+1];
__device__ int   g_cur[Nn];
__device__ int   g_eidx[ET];
__device__ float g_hlin[Nn*HF];
__device__ float g_asrc[Nn*NH];
__device__ float g_adst[Nn*NH];
__device__ float g_h[Nn*DHID];

__device__ __forceinline__ float eluf(float x){ return x > 0.f ? x : expm1f(x); }
__device__ __forceinline__ float dot4(float4 a, float4 b){
  return a.x*b.x + a.y*b.y + a.z*b.z + a.w*b.w;
}

// -------- zero counters --------
__global__ void k_zero(){
  int t = blockIdx.x*256 + threadIdx.x;
  if (t < Nn){ g_deg[t] = 0; g_cur[t] = 0; }
}

// -------- initial linear 1: tmp128 = elu(bn(x@w1+b1)) --------
__global__ void k_lin1(const float* __restrict__ x, const float* __restrict__ w,
                       const float* __restrict__ b, const float* __restrict__ g,
                       const float* __restrict__ be){
  __shared__ float xs[DIN];
  int r = blockIdx.x, tid = threadIdx.x;
  if (tid < DIN) xs[tid] = x[r*DIN + tid];
  __syncthreads();
  float acc = b[tid];
  #pragma unroll 8
  for (int d = 0; d < DIN; d++) acc += xs[d]*w[d*DHID + tid];
  acc = g[tid]*acc*BNS + be[tid];
  g_tmp128[r*DHID + tid] = eluf(acc);
}

// -------- initial linear 2 + P = emb@lp_A --------
__global__ void k_lin2(const float* __restrict__ w, const float* __restrict__ b,
                       const float* __restrict__ g, const float* __restrict__ be,
                       const float* __restrict__ lpA){
  __shared__ float ts[8][DHID];
  __shared__ float es[8][DE];
  int r0 = blockIdx.x*8;
  int tid = threadIdx.x;
  for (int idx = tid; idx < 8*DHID; idx += 128)
    ts[idx/DHID][idx%DHID] = g_tmp128[(r0 + idx/DHID)*DHID + (idx%DHID)];
  __syncthreads();
  int rr = tid >> 4, c = tid & 15;
  float acc = b[c];
  #pragma unroll 8
  for (int d = 0; d < DHID; d++) acc += ts[rr][d]*w[d*DE + c];
  acc = g[c]*acc*BNS + be[c];
  acc = eluf(acc);
  es[rr][c] = acc;
  g_emb[(r0+rr)*DE + c] = acc;
  __syncthreads();
  float p = 0.f;
  #pragma unroll
  for (int d = 0; d < DE; d++) p += es[rr][d]*lpA[d*DE + c];
  g_P[(r0+rr)*DE + c] = p;
}

// -------- link logits: L[i,j]=P_i.emb_j+b for j>i, triu-packed --------
__global__ void k_link(float* __restrict__ out, const float* __restrict__ lp_b){
  const int RT = 32;
  __shared__ float4 Ps[RT*4];
  __shared__ int base[RT];
  int i0 = blockIdx.x * RT;
  int tid = threadIdx.x;
  const float4* pF = (const float4*)g_P;
  const float4* eF = (const float4*)g_emb;
  if (tid < RT*4) Ps[tid] = pF[i0*4 + tid];
  if (tid < RT){
    int i = i0 + tid;
    base[tid] = i*(Nn-1) - (i*(i-1))/2 - i - 1;
  }
  __syncthreads();
  float bb = lp_b[0];
  int s0 = blockIdx.y * (Nn/4);
  int s1 = s0 + (Nn/4);
  int jstart = max(s0, i0+1);
  float* ll = out + LL_OFF;
  for (int j = jstart + tid; j < s1; j += 256){
    float4 e0 = eF[j*4+0], e1 = eF[j*4+1], e2 = eF[j*4+2], e3 = eF[j*4+3];
    int imax = min(RT, j - i0);
    for (int ii = 0; ii < imax; ii++){
      float4 p0 = Ps[ii*4+0], p1 = Ps[ii*4+1], p2 = Ps[ii*4+2], p3 = Ps[ii*4+3];
      float v = bb + (dot4(p0,e0)+dot4(p1,e1)) + (dot4(p2,e2)+dot4(p3,e3));
      ll[base[ii] + j] = v;
    }
  }
}

// -------- partial top-7 per (row, column-chunk) --------
__global__ void k_topk(){
  __shared__ float4 se[256*4];
  __shared__ float4 sp[256*4];
  int tid = threadIdx.x;
  int i = blockIdx.x*256 + tid;
  const float4* eF = (const float4*)g_emb;
  const float4* pF = (const float4*)g_P;
  float4 ei0 = eF[i*4+0], ei1 = eF[i*4+1], ei2 = eF[i*4+2], ei3 = eF[i*4+3];
  float4 pi0 = pF[i*4+0], pi1 = pF[i*4+1], pi2 = pF[i*4+2], pi3 = pF[i*4+3];
  float tv[TOPK]; int tix[TOPK];
  #pragma unroll
  for (int s = 0; s < TOPK; s++){ tv[s] = -3.4e38f; tix[s] = 0x7fffffff; }
  int c0 = blockIdx.y * CHUNK;
  for (int t = 0; t < CHUNK/256; t++){
    int cb = c0 + t*256;
    __syncthreads();
    #pragma unroll
    for (int q = 0; q < 4; q++){
      int idx = tid + q*256;
      se[idx] = eF[cb*4 + idx];
      sp[idx] = pF[cb*4 + idx];
    }
    __syncthreads();
    for (int jj = 0; jj < 256; jj++){
      int j = cb + jj;
      if (j == i) continue;
      float v;
      if (j > i){
        v = (dot4(pi0,se[jj*4+0])+dot4(pi1,se[jj*4+1]))
          + (dot4(pi2,se[jj*4+2])+dot4(pi3,se[jj*4+3]));
      } else {
        v = (dot4(sp[jj*4+0],ei0)+dot4(sp[jj*4+1],ei1))
          + (dot4(sp[jj*4+2],ei2)+dot4(sp[jj*4+3],ei3));
      }
      if (v > tv[TOPK-1] || (v == tv[TOPK-1] && j < tix[TOPK-1])){
        float cv = v; int ci = j;
        #pragma unroll
        for (int s = 0; s < TOPK; s++){
          bool bt = (cv > tv[s]) || (cv == tv[s] && ci < tix[s]);
          float nv = bt ? cv : tv[s]; int ni = bt ? ci : tix[s];
          cv = bt ? tv[s] : cv; ci = bt ? tix[s] : ci;
          tv[s] = nv; tix[s] = ni;
        }
      }
    }
  }
  int pb = (i*NCHUNK + blockIdx.y)*TOPK;
  #pragma unroll
  for (int s = 0; s < TOPK; s++){ g_ptv[pb+s] = tv[s]; g_pti[pb+s] = tix[s]; }
}

// -------- merge partials -> sel (descending, ties: lower index) --------
__global__ void k_merge(){
  int r = blockIdx.x*256 + threadIdx.x;
  int base = r*NCHUNK*TOPK;
  float pv = 3.4e38f; int pi = -1;
  for (int k = 0; k < TOPK; k++){
    float bv = -3.4e38f; int bi = 0x7fffffff;
    for (int c = 0; c < NCHUNK*TOPK; c++){
      float v = g_ptv[base+c]; int ix = g_pti[base+c];
      bool worse  = (v < pv) || (v == pv && ix > pi);
      bool better = (v > bv) || (v == bv && ix < bi);
      if (worse && better){ bv = v; bi = ix; }
    }
    g_sel[r*TOPK + k] = bi;
    pv = bv; pi = bi;
  }
}

// -------- edge build + dedup + degree count + edge_index output --------
__global__ void k_edges(float* __restrict__ out){
  int e = blockIdx.x*256 + threadIdx.x;
  if (e >= ET) return;
  int s, d, valid = 1;
  if (e < EK){
    int i = e / TOPK;
    int j = g_sel[e];
    if (j < i){
      #pragma unroll
      for (int kk = 0; kk < TOPK; kk++)
        if (g_sel[j*TOPK + kk] == i) valid = 0;
    }
    s = min(i, j); d = max(i, j);
  } else {
    s = d = e - EK;
  }
  g_src[e] = s; g_dst[e] = d; g_val[e] = valid;
  out[EI_OFF + e]      = (float)s;
  out[EI_OFF + ET + e] = (float)d;
  if (valid) atomicAdd(&g_deg[d], 1);
}

// -------- exclusive scan of degrees (single block) --------
__global__ void k_scan(){
  __shared__ int ssum[256];
  int t = threadIdx.x;
  int base = t*32;
  int loc[32];
  int s = 0;
  #pragma unroll
  for (int c = 0; c < 32; c++){ loc[c] = s; s += g_deg[base + c]; }
  ssum[t] = s;
  __syncthreads();
  for (int ofs = 1; ofs < 256; ofs <<= 1){
    int v = (t >= ofs) ? ssum[t-ofs] : 0;
    __syncthreads();
    ssum[t] += v;
    __syncthreads();
  }
  int excl = ssum[t] - s;
  #pragma unroll
  for (int c = 0; c < 32; c++) g_off[base + c] = excl + loc[c];
  if (t == 255) g_off[Nn] = ssum[255];
}

// -------- scatter valid edges into CSR-by-dst --------
__global__ void k_scatter(){
  int e = blockIdx.x*256 + threadIdx.x;
  if (e >= ET || !g_val[e]) return;
  int d = g_dst[e];
  int p = atomicAdd(&g_cur[d], 1);
  g_eidx[g_off[d] + p] = e;
}

// -------- feature GEMM: hlin = feat @ W  ([N,KD]x[KD,512]) --------
template<int KD, bool USE_GH>
__global__ void k_feat(const float* __restrict__ xin, const float* __restrict__ W){
  __shared__ float fsT[KD][16];
  const float* feat = USE_GH ? g_h : xin;
  int r0 = blockIdx.x*16;
  int tid = threadIdx.x;
  for (int idx = tid; idx < 16*KD; idx += 128){
    int r = idx / KD, d = idx % KD;
    fsT[d][r] = feat[(r0+r)*KD + d];
  }
  __syncthreads();
  int c = blockIdx.y*128 + tid;
  float acc[16];
  #pragma unroll
  for (int r = 0; r < 16; r++) acc[r] = 0.f;
  for (int d = 0; d < KD; d++){
    float w = W[d*HF + c];
    const float4* fp = (const float4*)&fsT[d][0];
    float4 f0 = fp[0], f1 = fp[1], f2 = fp[2], f3 = fp[3];
    acc[0]  += f0.x*w; acc[1]  += f0.y*w; acc[2]  += f0.z*w; acc[3]  += f0.w*w;
    acc[4]  += f1.x*w; acc[5]  += f1.y*w; acc[6]  += f1.z*w; acc[7]  += f1.w*w;
    acc[8]  += f2.x*w; acc[9]  += f2.y*w; acc[10] += f2.z*w; acc[11] += f2.w*w;
    acc[12] += f3.x*w; acc[13] += f3.y*w; acc[14] += f3.z*w; acc[15] += f3.w*w;
  }
  #pragma unroll
  for (int r = 0; r < 16; r++) g_hlin[(size_t)(r0+r)*HF + c] = acc[r];
}

// -------- attention coefficients: asrc/adst[n,h] --------
__global__ void k_attn(const float* __restrict__ as, const float* __restrict__ ad){
  int n = blockIdx.x;
  int h = threadIdx.x >> 5, l = threadIdx.x & 31;
  const float* hp = g_hlin + (size_t)n*HF + h*DHID;
  float s1 = 0.f, s2 = 0.f;
  #pragma unroll
  for (int t = 0; t < 4; t++){
    float v = hp[l + 32*t];
    s1 += v*as[h*DHID + l + 32*t];
    s2 += v*ad[h*DHID + l + 32*t];
  }
  for (int m = 16; m; m >>= 1){
    s1 += __shfl_xor_sync(0xffffffffu, s1, m);
    s2 += __shfl_xor_sync(0xffffffffu, s2, m);
  }
  if (!l){ g_asrc[n*NH + h] = s1; g_adst[n*NH + h] = s2; }
}

// -------- GAT aggregation: warp per dst node, fused mean+bias+bn+elu --------
__global__ void k_gat(const float* __restrict__ bias, const float* __restrict__ bng,
                      const float* __restrict__ bnb){
  int n = (blockIdx.x*blockDim.x + threadIdx.x) >> 5;
  int lane = threadIdx.x & 31;
  if (n >= Nn) return;
  int beg = g_off[n], end = g_off[n+1];
  float adn[NH];
  #pragma unroll
  for (int h = 0; h < NH; h++) adn[h] = g_adst[n*NH + h];
  // pass 1: per-head max
  float mx[NH];
  #pragma unroll
  for (int h = 0; h < NH; h++) mx[h] = -1e30f;
  for (int idx = beg + lane; idx < end; idx += 32){
    int s = g_src[g_eidx[idx]];
    #pragma unroll
    for (int h = 0; h < NH; h++){
      float al = g_asrc[s*NH + h] + adn[h];
      al = al > 0.f ? al : 0.2f*al;
      mx[h] = fmaxf(mx[h], al);
    }
  }
  #pragma unroll
  for (int h = 0; h < NH; h++)
    for (int m = 16; m; m >>= 1) mx[h] = fmaxf(mx[h], __shfl_xor_sync(0xffffffffu, mx[h], m));
  // pass 2: denominator
  float den[NH];
  #pragma unroll
  for (int h = 0; h < NH; h++) den[h] = 0.f;
  for (int idx = beg + lane; idx < end; idx += 32){
    int s = g_src[g_eidx[idx]];
    #pragma unroll
    for (int h = 0; h < NH; h++){
      float al = g_asrc[s*NH + h] + adn[h];
      al = al > 0.f ? al : 0.2f*al;
      den[h] += expf(al - mx[h]);
    }
  }
  #pragma unroll
  for (int h = 0; h < NH; h++)
    for (int m = 16; m; m >>= 1) den[h] += __shfl_xor_sync(0xffffffffu, den[h], m);
  // pass 3: weighted accumulation over edges (whole warp per edge)
  float acc[16];
  #pragma unroll
  for (int t = 0; t < 16; t++) acc[t] = 0.f;
  for (int idx = beg; idx < end; idx++){
    int s = g_src[g_eidx[idx]];
    float alpha[NH];
    #pragma unroll
    for (int h = 0; h < NH; h++){
      float al = g_asrc[s*NH + h] + adn[h];
      al = al > 0.f ? al : 0.2f*al;
      alpha[h] = expf(al - mx[h]) / den[h];
    }
    const float* hp = g_hlin + (size_t)s*HF;
    #pragma unroll
    for (int t = 0; t < 16; t++) acc[t] += hp[lane + 32*t]*alpha[t>>2];
  }
  #pragma unroll
  for (int q = 0; q < 4; q++){
    int f = lane + 32*q;
    float o = (acc[q] + acc[q+4] + acc[q+8] + acc[q+12])*0.25f;
    o += bias[f];
    o = bng[f]*o*BNS + bnb[f];
    g_h[n*DHID + f] = eluf(o);
  }
}

// -------- out0 = bn(h@f0_w+f0_b) --------
__global__ void k_out0(float* __restrict__ out, const float* __restrict__ w,
                       const float* __restrict__ b, const float* __restrict__ bg,
                       const float* __restrict__ bb){
  __shared__ float hs[DHID];
  int r = blockIdx.x, tid = threadIdx.x;
  for (int idx = tid; idx < DHID; idx += 64) hs[idx] = g_h[r*DHID + idx];
  __syncthreads();
  float acc = b[tid];
  #pragma unroll 8
  for (int d = 0; d < DHID; d++) acc += hs[d]*w[d*64 + tid];
  acc = bg[tid]*acc*BNS + bb[tid];
  out[OUT0_OFF + r*64 + tid] = acc;
}

// -------- out1 = bn(elu(out0@f1_w+f1_b)) --------
__global__ void k_out1(float* __restrict__ out, const float* __restrict__ w,
                       const float* __restrict__ b, const float* __restrict__ bg,
                       const float* __restrict__ bb){
  __shared__ float os[8][64];
  int r0 = blockIdx.x*8, tid = threadIdx.x;
  for (int idx = tid; idx < 8*64; idx += 128)
    os[idx/64][idx%64] = out[OUT0_OFF + (r0 + idx/64)*64 + (idx%64)];
  __syncthreads();
  int rr = tid >> 4, c = tid & 15;
  float acc = b[c];
  #pragma unroll 8
  for (int d = 0; d < 64; d++) acc += os[rr][d]*w[d*DE + c];
  acc = eluf(acc);
  acc = bg[c]*acc*BNS + bb[c];
  out[OUT1_OFF + (r0+rr)*DE + c] = acc;
}

extern "C" void kernel_launch(void* const* d_in, const int* in_sizes, int n_in,
                              void* d_out, int out_size) {
  const float* x      = (const float*)d_in[0];
  const float* il_w1  = (const float*)d_in[1];
  const float* il_b1  = (const float*)d_in[2];
  const float* il_g1  = (const float*)d_in[3];
  const float* il_be1 = (const float*)d_in[4];
  const float* il_w2  = (const float*)d_in[5];
  const float* il_b2  = (const float*)d_in[6];
  const float* il_g2  = (const float*)d_in[7];
  const float* il_be2 = (const float*)d_in[8];
  const float* lp_A   = (const float*)d_in[9];
  const float* lp_b   = (const float*)d_in[10];
  const float* g0_w   = (const float*)d_in[11];
  const float* g0_as  = (const float*)d_in[12];
  const float* g0_ad  = (const float*)d_in[13];
  const float* g0_b   = (const float*)d_in[14];
  const float* bn0_g  = (const float*)d_in[15];
  const float* bn0_b  = (const float*)d_in[16];
  const float* g1_w   = (const float*)d_in[17];
  const float* g1_as  = (const float*)d_in[18];
  const float* g1_ad  = (const float*)d_in[19];
  const float* g1_b   = (const float*)d_in[20];
  const float* bn1_g  = (const float*)d_in[21];
  const float* bn1_b  = (const float*)d_in[22];
  const float* f0_w   = (const float*)d_in[23];
  const float* f0_b   = (const float*)d_in[24];
  const float* fbn0_g = (const float*)d_in[25];
  const float* fbn0_b = (const float*)d_in[26];
  const float* f1_w   = (const float*)d_in[27];
  const float* f1_b   = (const float*)d_in[28];
  const float* fbn1_g = (const float*)d_in[29];
  const float* fbn1_b = (const float*)d_in[30];
  float* out = (float*)d_out;

  k_zero<<<Nn/256, 256>>>();
  k_lin1<<<Nn, DHID>>>(x, il_w1, il_b1, il_g1, il_be1);
  k_lin2<<<Nn/8, 128>>>(il_w2, il_b2, il_g2, il_be2, lp_A);
  k_link<<<dim3(Nn/32, 4), 256>>>(out, lp_b);
  k_topk<<<dim3(Nn/256, NCHUNK), 256>>>();
  k_merge<<<Nn/256, 256>>>();
  k_edges<<<ET/256, 256>>>(out);
  k_scan<<<1, 256>>>();
  k_scatter<<<ET/256, 256>>>();
  // GAT layer 0 (input = x)
  k_feat<DIN, false><<<dim3(Nn/16, HF/128), 128>>>(x, g0_w);
  k_attn<<<Nn, 128>>>(g0_as, g0_ad);
  k_gat<<<(Nn*32)/256, 256>>>(g0_b, bn0_g, bn0_b);
  // GAT layer 1 (input = g_h)
  k_feat<DHID, true><<<dim3(Nn/16, HF/128), 128>>>(x, g1_w);
  k_attn<<<Nn, 128>>>(g1_as, g1_ad);
  k_gat<<<(Nn*32)/256, 256>>>(g1_b, bn1_g, bn1_b);
  // heads
  k_out0<<<Nn, 64>>>(out, f0_w, f0_b, fbn0_g, fbn0_b);
  k_out1<<<Nn/8, 128>>>(out, f1_w, f1_b, fbn1_g, fbn1_b);
}